// round 1
// baseline (speedup 1.0000x reference)
#include <cuda_runtime.h>

// Problem constants
#define BS   16      // batches
#define DD   4096    // D (spatial, reduction dim for P)
#define NN   512     // N (channels)
#define RR   16      // rank
#define EPSV 1e-6f
#define INVT 100.0f

#define NSLICE 8     // d-slices for P partials

// ---------------- scratch (device globals; no allocation allowed) ----------------
__device__ float g_bases[BS * DD * RR];          // 4 MB working bases
__device__ float g_coef [BS * NN * RR];          // 512 KB
__device__ float g_Ppart[BS * NSLICE * NN * RR]; // 4 MB partial P
__device__ float g_btb  [BS * RR * RR];
__device__ float g_ctc  [BS * RR * RR];

// ---------------- small helpers ----------------
__device__ __forceinline__ void load16(const float* __restrict__ src, float* v) {
    const float4* s4 = reinterpret_cast<const float4*>(src);
#pragma unroll
    for (int q = 0; q < 4; ++q) {
        float4 t = s4[q];
        v[4*q+0] = t.x; v[4*q+1] = t.y; v[4*q+2] = t.z; v[4*q+3] = t.w;
    }
}
__device__ __forceinline__ void store16(float* __restrict__ dst, const float* v) {
    float4* d4 = reinterpret_cast<float4*>(dst);
#pragma unroll
    for (int q = 0; q < 4; ++q)
        d4[q] = make_float4(v[4*q+0], v[4*q+1], v[4*q+2], v[4*q+3]);
}

// ---------------- init / utility kernels ----------------
__global__ void k_copy_bases(const float* __restrict__ src) {
    size_t i = (size_t)blockIdx.x * 256 + threadIdx.x;  // grid covers BS*DD*RR/4 float4s
    reinterpret_cast<float4*>(g_bases)[i] = reinterpret_cast<const float4*>(src)[i];
}

__global__ void k_zero_small() {
    int i = blockIdx.x * 256 + threadIdx.x;   // grid: 16 x 256 == BS*256
    g_btb[i] = 0.f;
    g_ctc[i] = 0.f;
}

// ---------------- Gram matrix: G = A^T A, A is [L][16] per batch ----------------
// grid (nslices, BS), block 256. thread t: r=t&15, s-quad sq=(t>>4)&3, substripe sub=t>>6
__device__ __forceinline__ void gram_body(const float* __restrict__ A,
                                          float* __restrict__ G, int L) {
    const int b  = blockIdx.y;
    const int sl = blockIdx.x;
    const int t  = threadIdx.x;
    const int LS = L / gridDim.x;
    const int r   = t & 15;
    const int sq  = (t >> 4) & 3;
    const int sub = t >> 6;

    const float* Ab = A + (size_t)b * L * RR;
    float4 acc = make_float4(0.f, 0.f, 0.f, 0.f);
    const int dend = sl * LS + LS;
    for (int d = sl * LS + sub; d < dend; d += 4) {
        const float* row = Ab + (size_t)d * RR;
        float4 aq = *reinterpret_cast<const float4*>(row + sq * 4);
        float  ar = row[r];
        acc.x = fmaf(ar, aq.x, acc.x);
        acc.y = fmaf(ar, aq.y, acc.y);
        acc.z = fmaf(ar, aq.z, acc.z);
        acc.w = fmaf(ar, aq.w, acc.w);
    }
    __shared__ float4 red[256];
    red[t] = acc;
    __syncthreads();
    if (t < 64) {
        float4 a0 = red[t], a1 = red[t + 64], a2 = red[t + 128], a3 = red[t + 192];
        float sx = a0.x + a1.x + a2.x + a3.x;
        float sy = a0.y + a1.y + a2.y + a3.y;
        float sz = a0.z + a1.z + a2.z + a3.z;
        float sw = a0.w + a1.w + a2.w + a3.w;
        int rr_ = t & 15, sq_ = t >> 4;
        float* g = G + b * 256 + rr_ * 16 + sq_ * 4;
        atomicAdd(g + 0, sx); atomicAdd(g + 1, sy);
        atomicAdd(g + 2, sz); atomicAdd(g + 3, sw);
    }
}
__global__ void k_btb() { gram_body(g_bases, g_btb, DD); }   // grid (8, BS)
__global__ void k_ctc() { gram_body(g_coef,  g_ctc, NN); }   // grid (2, BS)

// ---------------- P pass: Ppart[b][sl][n][r] = sum_{d in slice} x[b][n][d]*bases[b][d][r] ----------------
// grid (4 n-chunks, NSLICE d-slices, BS), block 128. Thread owns one n row.
__global__ void k_pmat(const float* __restrict__ x) {
    const int tid = threadIdx.x;
    const int nc  = blockIdx.x;   // 0..3   (128 n each)
    const int ds  = blockIdx.y;   // 0..7   (512 d each)
    const int b   = blockIdx.z;

    __shared__ float xs[128][33];   // padded to kill bank conflicts
    __shared__ float bss[32 * RR];

    float acc[16];
#pragma unroll
    for (int r = 0; r < 16; ++r) acc[r] = 0.f;

    const float* xb = x + ((size_t)b * NN + (size_t)nc * 128) * DD;
    const float* bb = g_bases + (size_t)b * DD * RR;

    const int dbase = ds * 512;
    for (int t0 = dbase; t0 < dbase + 512; t0 += 32) {
        // stage x tile [128 n][32 d] (coalesced 128B rows)
        for (int i = tid; i < 128 * 32; i += 128) {
            int row = i >> 5, col = i & 31;
            xs[row][col] = xb[(size_t)row * DD + t0 + col];
        }
        // stage bases tile [32 d][16 r]
        for (int i = tid; i < 32 * RR; i += 128)
            bss[i] = bb[(size_t)t0 * RR + i];
        __syncthreads();
#pragma unroll
        for (int j = 0; j < 32; ++j) {
            float xv = xs[tid][j];
            const float4* b4 = reinterpret_cast<const float4*>(&bss[j * RR]);
#pragma unroll
            for (int q = 0; q < 4; ++q) {
                float4 bq = b4[q];   // broadcast across warp (threads differ in n)
                acc[4*q+0] = fmaf(xv, bq.x, acc[4*q+0]);
                acc[4*q+1] = fmaf(xv, bq.y, acc[4*q+1]);
                acc[4*q+2] = fmaf(xv, bq.z, acc[4*q+2]);
                acc[4*q+3] = fmaf(xv, bq.w, acc[4*q+3]);
            }
        }
        __syncthreads();
    }
    const int n = nc * 128 + tid;
    store16(g_Ppart + (((size_t)b * NSLICE + ds) * NN + n) * RR, acc);
}

// ---------------- coef kernels (reduce P partials, then update) ----------------
__device__ __forceinline__ void gather_P(int b, int n, float* p) {
#pragma unroll
    for (int r = 0; r < 16; ++r) p[r] = 0.f;
#pragma unroll
    for (int sl = 0; sl < NSLICE; ++sl) {
        const float4* pp = reinterpret_cast<const float4*>(
            g_Ppart + (((size_t)b * NSLICE + sl) * NN + n) * RR);
#pragma unroll
        for (int q = 0; q < 4; ++q) {
            float4 v = pp[q];
            p[4*q+0] += v.x; p[4*q+1] += v.y; p[4*q+2] += v.z; p[4*q+3] += v.w;
        }
    }
}

// coef = softmax(INVT * P) over r.  grid (4, BS), block 128.
__global__ void k_coef_init() {
    const int tid = threadIdx.x;
    const int b = blockIdx.y;
    const int n = blockIdx.x * 128 + tid;
    float p[16];
    gather_P(b, n, p);
    float m = p[0];
#pragma unroll
    for (int r = 1; r < 16; ++r) m = fmaxf(m, p[r]);
    float e[16]; float s = 0.f;
#pragma unroll
    for (int r = 0; r < 16; ++r) { e[r] = __expf(INVT * (p[r] - m)); s += e[r]; }
    float inv = 1.f / s;
#pragma unroll
    for (int r = 0; r < 16; ++r) e[r] *= inv;
    store16(g_coef + ((size_t)b * NN + n) * RR, e);
}

// coef = coef * P / (coef @ BtB + eps).  grid (4, BS), block 128.
__global__ void k_coef_upd() {
    __shared__ float btbs[256];
    const int tid = threadIdx.x;
    const int b = blockIdx.y;
    const int n = blockIdx.x * 128 + tid;
    for (int i = tid; i < 256; i += 128) btbs[i] = g_btb[b * 256 + i];
    __syncthreads();

    float p[16];
    gather_P(b, n, p);
    float cf[16];
    load16(g_coef + ((size_t)b * NN + n) * RR, cf);

    float den[16];
#pragma unroll
    for (int s2 = 0; s2 < 16; ++s2) den[s2] = 0.f;
#pragma unroll
    for (int r = 0; r < 16; ++r) {
        float c = cf[r];
        const float* row = &btbs[r * 16];
#pragma unroll
        for (int s2 = 0; s2 < 16; ++s2) den[s2] = fmaf(c, row[s2], den[s2]);
    }
#pragma unroll
    for (int r = 0; r < 16; ++r) cf[r] = cf[r] * p[r] / (den[r] + EPSV);
    store16(g_coef + ((size_t)b * NN + n) * RR, cf);
}

// ---------------- bases pass: Q[d][r] = sum_n x[b][n][d]*coef[n][r]; then update ----------------
// grid (16 d-chunks, BS), block 256, thread owns one d.
__global__ void k_bases_upd(const float* __restrict__ x) {
    __shared__ float cfs[NN * RR];   // 32 KB full coef for this batch
    __shared__ float ctcs[256];
    const int tid = threadIdx.x;
    const int dc  = blockIdx.x;
    const int b   = blockIdx.y;
    {
        float4* dst = reinterpret_cast<float4*>(cfs);
        const float4* src = reinterpret_cast<const float4*>(g_coef + (size_t)b * NN * RR);
        for (int i = tid; i < NN * RR / 4; i += 256) dst[i] = src[i];
        if (tid < 256) ctcs[tid] = g_ctc[b * 256 + tid];
    }
    __syncthreads();

    const int d = dc * 256 + tid;
    float acc[16];
#pragma unroll
    for (int r = 0; r < 16; ++r) acc[r] = 0.f;

    const float* xb = x + (size_t)b * NN * DD + d;
#pragma unroll 4
    for (int n = 0; n < NN; ++n) {
        float xv = xb[(size_t)n * DD];                 // coalesced across warp
        const float4* c4 = reinterpret_cast<const float4*>(&cfs[n * RR]); // broadcast
#pragma unroll
        for (int q = 0; q < 4; ++q) {
            float4 c = c4[q];
            acc[4*q+0] = fmaf(xv, c.x, acc[4*q+0]);
            acc[4*q+1] = fmaf(xv, c.y, acc[4*q+1]);
            acc[4*q+2] = fmaf(xv, c.z, acc[4*q+2]);
            acc[4*q+3] = fmaf(xv, c.w, acc[4*q+3]);
        }
    }

    float* brow = g_bases + ((size_t)b * DD + d) * RR;
    float bs[16];
    load16(brow, bs);
    float den[16];
#pragma unroll
    for (int s2 = 0; s2 < 16; ++s2) den[s2] = 0.f;
#pragma unroll
    for (int r = 0; r < 16; ++r) {
        float bv = bs[r];
        const float* row = &ctcs[r * 16];
#pragma unroll
        for (int s2 = 0; s2 < 16; ++s2) den[s2] = fmaf(bv, row[s2], den[s2]);
    }
#pragma unroll
    for (int r = 0; r < 16; ++r) bs[r] = bs[r] * acc[r] / (den[r] + EPSV);
    store16(brow, bs);
}

// ---------------- reconstruction: out[b][n][d] = sum_r bases[d][r]*coef[n][r] ----------------
// grid (16 d-chunks, BS), block 256, thread owns one d.
__global__ void k_out(float* __restrict__ out) {
    __shared__ float cfs[NN * RR];
    const int tid = threadIdx.x;
    const int dc  = blockIdx.x;
    const int b   = blockIdx.y;
    {
        float4* dst = reinterpret_cast<float4*>(cfs);
        const float4* src = reinterpret_cast<const float4*>(g_coef + (size_t)b * NN * RR);
        for (int i = tid; i < NN * RR / 4; i += 256) dst[i] = src[i];
    }
    __syncthreads();

    const int d = dc * 256 + tid;
    float bs[16];
    load16(g_bases + ((size_t)b * DD + d) * RR, bs);

    float* ob = out + (size_t)b * NN * DD + d;
#pragma unroll 2
    for (int n = 0; n < NN; ++n) {
        const float4* c4 = reinterpret_cast<const float4*>(&cfs[n * RR]);
        float o0 = 0.f, o1 = 0.f, o2 = 0.f, o3 = 0.f;
#pragma unroll
        for (int q = 0; q < 4; ++q) {
            float4 c = c4[q];
            o0 = fmaf(bs[4*q+0], c.x, o0);
            o1 = fmaf(bs[4*q+1], c.y, o1);
            o2 = fmaf(bs[4*q+2], c.z, o2);
            o3 = fmaf(bs[4*q+3], c.w, o3);
        }
        ob[(size_t)n * DD] = (o0 + o1) + (o2 + o3);
    }
}

// ---------------- launch ----------------
extern "C" void kernel_launch(void* const* d_in, const int* in_sizes, int n_in,
                              void* d_out, int out_size) {
    (void)in_sizes; (void)n_in; (void)out_size;
    const float* x     = (const float*)d_in[0];   // (16, 512, 4096) f32
    const float* bases = (const float*)d_in[1];   // (16, 4096, 16) f32
    float* out = (float*)d_out;                   // (16, 512, 4096) f32

    // working copy of bases
    k_copy_bases<<<(BS * DD * RR / 4) / 256, 256>>>(bases);

    // coef init: P = X^T B0, coef = softmax(100*P)
    k_pmat<<<dim3(4, NSLICE, BS), 128>>>(x);
    k_coef_init<<<dim3(4, BS), 128>>>();

    for (int it = 0; it < 7; ++it) {
        k_zero_small<<<16, 256>>>();
        k_btb<<<dim3(8, BS), 256>>>();
        k_pmat<<<dim3(4, NSLICE, BS), 128>>>(x);
        k_coef_upd<<<dim3(4, BS), 128>>>();
        k_ctc<<<dim3(2, BS), 256>>>();
        k_bases_upd<<<dim3(16, BS), 256>>>(x);
    }

    // final compute_coef
    k_zero_small<<<16, 256>>>();
    k_btb<<<dim3(8, BS), 256>>>();
    k_pmat<<<dim3(4, NSLICE, BS), 128>>>(x);
    k_coef_upd<<<dim3(4, BS), 128>>>();

    // reconstruction
    k_out<<<dim3(16, BS), 256>>>(out);
}

// round 2
// speedup vs baseline: 1.6599x; 1.6599x over previous
#include <cuda_runtime.h>

#define BS   16
#define DD   4096
#define NN   512
#define RR   16
#define EPSV 1e-6f
#define INVT 100.0f

#define NSLICE 16    // d-slices for P partials (256 d each)
#define GBS    8     // btb gram slices
#define GCS    4     // ctc gram slices
#define NSPL   2     // n-split for Q pass

// ---------------- scratch ----------------
__device__ float g_bases[BS * DD * RR];            // 4 MB
__device__ float g_coef [BS * NN * RR];            // 512 KB
__device__ float g_Ppart[BS * NSLICE * NN * RR];   // 8 MB
__device__ float g_Qpart[BS * NSPL * DD * RR];     // 8 MB
__device__ float g_btbp [BS * GBS * 256];
__device__ float g_ctcp [BS * GCS * 256];

// ---------------- helpers ----------------
__device__ __forceinline__ void load16(const float* __restrict__ src, float* v) {
    const float4* s4 = reinterpret_cast<const float4*>(src);
#pragma unroll
    for (int q = 0; q < 4; ++q) {
        float4 t = s4[q];
        v[4*q+0] = t.x; v[4*q+1] = t.y; v[4*q+2] = t.z; v[4*q+3] = t.w;
    }
}
__device__ __forceinline__ void store16(float* __restrict__ dst, const float* v) {
    float4* d4 = reinterpret_cast<float4*>(dst);
#pragma unroll
    for (int q = 0; q < 4; ++q)
        d4[q] = make_float4(v[4*q+0], v[4*q+1], v[4*q+2], v[4*q+3]);
}
__device__ __forceinline__ void fma16(float* acc, float xv, const float* __restrict__ row) {
    const float4* b4 = reinterpret_cast<const float4*>(row);
#pragma unroll
    for (int q = 0; q < 4; ++q) {
        float4 bq = b4[q];
        acc[4*q+0] = fmaf(xv, bq.x, acc[4*q+0]);
        acc[4*q+1] = fmaf(xv, bq.y, acc[4*q+1]);
        acc[4*q+2] = fmaf(xv, bq.z, acc[4*q+2]);
        acc[4*q+3] = fmaf(xv, bq.w, acc[4*q+3]);
    }
}

// ---------------- init ----------------
__global__ void k_copy_bases(const float* __restrict__ src) {
    size_t i = (size_t)blockIdx.x * 256 + threadIdx.x;
    reinterpret_cast<float4*>(g_bases)[i] = reinterpret_cast<const float4*>(src)[i];
}

// ---------------- gram partials: Gp[b][sl][r][s] = sum_{d in slice} A[d][r]*A[d][s] ----------------
// grid (nsl, BS), block 256
__device__ __forceinline__ void gram_part(const float* __restrict__ A,
                                          float* __restrict__ Gp, int L, int nsl) {
    const int b  = blockIdx.y;
    const int sl = blockIdx.x;
    const int t  = threadIdx.x;
    const int LS = L / nsl;
    const int r   = t & 15;
    const int sq  = (t >> 4) & 3;
    const int sub = t >> 6;

    const float* Ab = A + (size_t)b * L * RR;
    float4 acc = make_float4(0.f, 0.f, 0.f, 0.f);
    const int dend = sl * LS + LS;
    for (int d = sl * LS + sub; d < dend; d += 4) {
        const float* row = Ab + (size_t)d * RR;
        float4 aq = *reinterpret_cast<const float4*>(row + sq * 4);
        float  ar = row[r];
        acc.x = fmaf(ar, aq.x, acc.x);
        acc.y = fmaf(ar, aq.y, acc.y);
        acc.z = fmaf(ar, aq.z, acc.z);
        acc.w = fmaf(ar, aq.w, acc.w);
    }
    __shared__ float4 red[256];
    red[t] = acc;
    __syncthreads();
    if (t < 64) {
        float4 a0 = red[t], a1 = red[t + 64], a2 = red[t + 128], a3 = red[t + 192];
        float4 s;
        s.x = a0.x + a1.x + a2.x + a3.x;
        s.y = a0.y + a1.y + a2.y + a3.y;
        s.z = a0.z + a1.z + a2.z + a3.z;
        s.w = a0.w + a1.w + a2.w + a3.w;
        int rr_ = t & 15, sq_ = t >> 4;
        *reinterpret_cast<float4*>(Gp + ((size_t)b * nsl + sl) * 256 + rr_ * 16 + sq_ * 4) = s;
    }
}
__global__ void k_btb() { gram_part(g_bases, g_btbp, DD, GBS); }  // grid (8, BS)
__global__ void k_ctc() { gram_part(g_coef,  g_ctcp, NN, GCS); }  // grid (4, BS)

// ---------------- P pass: Ppart[b][ds][n][r] over 256-d slices ----------------
// grid (4, NSLICE, BS), block 128
__global__ void __launch_bounds__(128) k_pmat(const float* __restrict__ x) {
    __shared__ float bss[256 * RR];   // 16 KB: full bases slice for this block
    __shared__ float xs[128][33];     // padded: conflict-free xs[tid][j]

    const int tid = threadIdx.x;
    const int nc  = blockIdx.x;
    const int ds  = blockIdx.y;
    const int b   = blockIdx.z;

    // stage bases slice once
    {
        const float4* s = reinterpret_cast<const float4*>(
            g_bases + ((size_t)b * DD + (size_t)ds * 256) * RR);
        float4* d = reinterpret_cast<float4*>(bss);
#pragma unroll
        for (int i = 0; i < 8; ++i) d[tid + i * 128] = s[tid + i * 128];
    }

    float acc[16];
#pragma unroll
    for (int r = 0; r < 16; ++r) acc[r] = 0.f;

    const float* xb = x + ((size_t)b * NN + (size_t)nc * 128) * DD + (size_t)ds * 256;

    for (int t0 = 0; t0 < 256; t0 += 32) {
        __syncthreads();
        // stage x tile [128 n][32 d] via float4 (coalesced: 8 lanes per row)
#pragma unroll
        for (int k = 0; k < 8; ++k) {
            int idx = tid + k * 128;
            int row = idx >> 3, c4 = idx & 7;
            float4 v = *reinterpret_cast<const float4*>(xb + (size_t)row * DD + t0 + c4 * 4);
            float* dp = &xs[row][c4 * 4];
            dp[0] = v.x; dp[1] = v.y; dp[2] = v.z; dp[3] = v.w;
        }
        __syncthreads();
#pragma unroll
        for (int j = 0; j < 32; ++j) {
            float xv = xs[tid][j];
            fma16(acc, xv, &bss[(t0 + j) * RR]);
        }
    }
    const int n = nc * 128 + tid;
    store16(g_Ppart + (((size_t)b * NSLICE + ds) * NN + n) * RR, acc);
}

// ---------------- coef kernels ----------------
__device__ __forceinline__ void gather_P(int b, int n, float* p) {
#pragma unroll
    for (int r = 0; r < 16; ++r) p[r] = 0.f;
#pragma unroll
    for (int sl = 0; sl < NSLICE; ++sl) {
        const float4* pp = reinterpret_cast<const float4*>(
            g_Ppart + (((size_t)b * NSLICE + sl) * NN + n) * RR);
#pragma unroll
        for (int q = 0; q < 4; ++q) {
            float4 v = pp[q];
            p[4*q+0] += v.x; p[4*q+1] += v.y; p[4*q+2] += v.z; p[4*q+3] += v.w;
        }
    }
}
__device__ __forceinline__ void reduce_btb(int b, int tid, float* btbs) {
    for (int j = tid; j < 256; j += 128) {
        float s = 0.f;
#pragma unroll
        for (int sl = 0; sl < GBS; ++sl) s += g_btbp[((size_t)b * GBS + sl) * 256 + j];
        btbs[j] = s;
    }
}
__device__ __forceinline__ void coef_mult_update(float* cf, const float* p, const float* btbs) {
    float den[16];
#pragma unroll
    for (int s2 = 0; s2 < 16; ++s2) den[s2] = 0.f;
#pragma unroll
    for (int r = 0; r < 16; ++r) {
        float c = cf[r];
        const float* row = &btbs[r * 16];
#pragma unroll
        for (int s2 = 0; s2 < 16; ++s2) den[s2] = fmaf(c, row[s2], den[s2]);
    }
#pragma unroll
    for (int r = 0; r < 16; ++r) cf[r] = cf[r] * p[r] / (den[r] + EPSV);
}

// softmax init + first multiplicative update fused (bases unchanged between them).
// grid (4, BS), block 128
__global__ void k_coef_initupd() {
    __shared__ float btbs[256];
    const int tid = threadIdx.x;
    const int b = blockIdx.y;
    const int n = blockIdx.x * 128 + tid;
    reduce_btb(b, tid, btbs);
    __syncthreads();

    float p[16];
    gather_P(b, n, p);
    float m = p[0];
#pragma unroll
    for (int r = 1; r < 16; ++r) m = fmaxf(m, p[r]);
    float cf[16]; float s = 0.f;
#pragma unroll
    for (int r = 0; r < 16; ++r) { cf[r] = __expf(INVT * (p[r] - m)); s += cf[r]; }
    float inv = 1.f / s;
#pragma unroll
    for (int r = 0; r < 16; ++r) cf[r] *= inv;

    coef_mult_update(cf, p, btbs);
    store16(g_coef + ((size_t)b * NN + n) * RR, cf);
}

// grid (4, BS), block 128
__global__ void k_coef_upd() {
    __shared__ float btbs[256];
    const int tid = threadIdx.x;
    const int b = blockIdx.y;
    const int n = blockIdx.x * 128 + tid;
    reduce_btb(b, tid, btbs);
    __syncthreads();

    float p[16];
    gather_P(b, n, p);
    float cf[16];
    load16(g_coef + ((size_t)b * NN + n) * RR, cf);
    coef_mult_update(cf, p, btbs);
    store16(g_coef + ((size_t)b * NN + n) * RR, cf);
}

// ---------------- Q pass: Qpart[b][h][d][r] = sum_{n in half} x[b][n][d]*coef[n][r] ----------------
// grid (32, NSPL, BS), block 128
__global__ void __launch_bounds__(128) k_qmat(const float* __restrict__ x) {
    __shared__ float cfs[256 * RR];   // 16 KB: coef half
    const int tid = threadIdx.x;
    const int dc  = blockIdx.x;
    const int h   = blockIdx.y;
    const int b   = blockIdx.z;
    {
        const float4* s = reinterpret_cast<const float4*>(
            g_coef + ((size_t)b * NN + (size_t)h * 256) * RR);
        float4* d = reinterpret_cast<float4*>(cfs);
#pragma unroll
        for (int i = 0; i < 8; ++i) d[tid + i * 128] = s[tid + i * 128];
    }
    __syncthreads();

    const int d = dc * 128 + tid;
    float acc[16];
#pragma unroll
    for (int r = 0; r < 16; ++r) acc[r] = 0.f;

    const float* xb = x + ((size_t)b * NN + (size_t)h * 256) * DD + d;
    for (int n0 = 0; n0 < 256; n0 += 16) {
        float xv[16];
#pragma unroll
        for (int u = 0; u < 16; ++u) xv[u] = xb[(size_t)(n0 + u) * DD];
#pragma unroll
        for (int u = 0; u < 16; ++u) fma16(acc, xv[u], &cfs[(n0 + u) * RR]);
    }
    store16(g_Qpart + (((size_t)b * NSPL + h) * DD + d) * RR, acc);
}

// merge Q partials + CtC reduce + bases multiplicative update. grid (16, BS), block 256
__global__ void k_bases_merge() {
    __shared__ float ctcs[256];
    const int tid = threadIdx.x;
    const int b   = blockIdx.y;
    {
        float s = 0.f;
#pragma unroll
        for (int sl = 0; sl < GCS; ++sl) s += g_ctcp[((size_t)b * GCS + sl) * 256 + tid];
        ctcs[tid] = s;
    }
    __syncthreads();

    const int d = blockIdx.x * 256 + tid;
    float q[16];
    load16(g_Qpart + (((size_t)b * NSPL + 0) * DD + d) * RR, q);
    {
        float q1[16];
        load16(g_Qpart + (((size_t)b * NSPL + 1) * DD + d) * RR, q1);
#pragma unroll
        for (int r = 0; r < 16; ++r) q[r] += q1[r];
    }
    float* brow = g_bases + ((size_t)b * DD + d) * RR;
    float bs[16];
    load16(brow, bs);
    float den[16];
#pragma unroll
    for (int s2 = 0; s2 < 16; ++s2) den[s2] = 0.f;
#pragma unroll
    for (int r = 0; r < 16; ++r) {
        float bv = bs[r];
        const float* row = &ctcs[r * 16];
#pragma unroll
        for (int s2 = 0; s2 < 16; ++s2) den[s2] = fmaf(bv, row[s2], den[s2]);
    }
#pragma unroll
    for (int r = 0; r < 16; ++r) bs[r] = bs[r] * q[r] / (den[r] + EPSV);
    store16(brow, bs);
}

// ---------------- reconstruction ----------------
// grid (32, BS), block 128
__global__ void __launch_bounds__(128) k_out(float* __restrict__ out) {
    __shared__ float cfs[NN * RR];   // 32 KB
    const int tid = threadIdx.x;
    const int dc  = blockIdx.x;
    const int b   = blockIdx.y;
    {
        const float4* s = reinterpret_cast<const float4*>(g_coef + (size_t)b * NN * RR);
        float4* d = reinterpret_cast<float4*>(cfs);
#pragma unroll
        for (int i = 0; i < 16; ++i) d[tid + i * 128] = s[tid + i * 128];
    }
    __syncthreads();

    const int d = dc * 128 + tid;
    float bs[16];
    load16(g_bases + ((size_t)b * DD + d) * RR, bs);

    float* ob = out + (size_t)b * NN * DD + d;
#pragma unroll 4
    for (int n = 0; n < NN; ++n) {
        const float4* c4 = reinterpret_cast<const float4*>(&cfs[n * RR]);
        float o0 = 0.f, o1 = 0.f, o2 = 0.f, o3 = 0.f;
#pragma unroll
        for (int q = 0; q < 4; ++q) {
            float4 c = c4[q];
            o0 = fmaf(bs[4*q+0], c.x, o0);
            o1 = fmaf(bs[4*q+1], c.y, o1);
            o2 = fmaf(bs[4*q+2], c.z, o2);
            o3 = fmaf(bs[4*q+3], c.w, o3);
        }
        ob[(size_t)n * DD] = (o0 + o1) + (o2 + o3);
    }
}

// ---------------- launch ----------------
extern "C" void kernel_launch(void* const* d_in, const int* in_sizes, int n_in,
                              void* d_out, int out_size) {
    (void)in_sizes; (void)n_in; (void)out_size;
    const float* x     = (const float*)d_in[0];
    const float* bases = (const float*)d_in[1];
    float* out = (float*)d_out;

    k_copy_bases<<<(BS * DD * RR / 4) / 256, 256>>>(bases);

    // P for bases0 + gram(bases0), then fused softmax-init + first coef update
    k_pmat<<<dim3(4, NSLICE, BS), 128>>>(x);
    k_btb <<<dim3(GBS, BS), 256>>>();
    k_coef_initupd<<<dim3(4, BS), 128>>>();

    // first bases update
    k_ctc <<<dim3(GCS, BS), 256>>>();
    k_qmat<<<dim3(32, NSPL, BS), 128>>>(x);
    k_bases_merge<<<dim3(16, BS), 256>>>();

    // remaining 6 NMF steps
    for (int it = 1; it < 7; ++it) {
        k_pmat<<<dim3(4, NSLICE, BS), 128>>>(x);
        k_btb <<<dim3(GBS, BS), 256>>>();
        k_coef_upd<<<dim3(4, BS), 128>>>();
        k_ctc <<<dim3(GCS, BS), 256>>>();
        k_qmat<<<dim3(32, NSPL, BS), 128>>>(x);
        k_bases_merge<<<dim3(16, BS), 256>>>();
    }

    // final compute_coef
    k_pmat<<<dim3(4, NSLICE, BS), 128>>>(x);
    k_btb <<<dim3(GBS, BS), 256>>>();
    k_coef_upd<<<dim3(4, BS), 128>>>();

    // reconstruction
    k_out<<<dim3(32, BS), 128>>>(out);
}

// round 3
// speedup vs baseline: 1.7335x; 1.0443x over previous
#include <cuda_runtime.h>

#define BS   16
#define DD   4096
#define NN   512
#define RR   16
#define EPSV 1e-6f
#define INVT 100.0f

#define NSLICE 8      // d-slices for P partials (512 d each)
#define NBTB   32     // btb gram partial slices (written by k_qmat / k_btb0)
#define NCTC   4      // ctc gram partial slices (written by coef kernels)

// ---------------- scratch ----------------
__device__ float g_bases[BS * DD * RR];            // 4 MB
__device__ float g_coef [BS * NN * RR];            // 512 KB
__device__ float g_Ppart[BS * NSLICE * NN * RR];   // 4 MB
__device__ float g_btbp [BS * NBTB * 256];         // 512 KB
__device__ float g_ctcp [BS * NCTC * 256];         // 64 KB

// ---------------- helpers ----------------
__device__ __forceinline__ void load16(const float* __restrict__ src, float* v) {
    const float4* s4 = reinterpret_cast<const float4*>(src);
#pragma unroll
    for (int q = 0; q < 4; ++q) {
        float4 t = s4[q];
        v[4*q+0] = t.x; v[4*q+1] = t.y; v[4*q+2] = t.z; v[4*q+3] = t.w;
    }
}
__device__ __forceinline__ void store16(float* __restrict__ dst, const float* v) {
    float4* d4 = reinterpret_cast<float4*>(dst);
#pragma unroll
    for (int q = 0; q < 4; ++q)
        d4[q] = make_float4(v[4*q+0], v[4*q+1], v[4*q+2], v[4*q+3]);
}
__device__ __forceinline__ void fma16(float* acc, float xv, const float* __restrict__ row) {
    const float4* b4 = reinterpret_cast<const float4*>(row);
#pragma unroll
    for (int q = 0; q < 4; ++q) {
        float4 bq = b4[q];
        acc[4*q+0] = fmaf(xv, bq.x, acc[4*q+0]);
        acc[4*q+1] = fmaf(xv, bq.y, acc[4*q+1]);
        acc[4*q+2] = fmaf(xv, bq.z, acc[4*q+2]);
        acc[4*q+3] = fmaf(xv, bq.w, acc[4*q+3]);
    }
}
// denominator: den[s] = sum_r v[r] * G[r][s]
__device__ __forceinline__ void mat16(float* den, const float* v, const float* __restrict__ G) {
#pragma unroll
    for (int s2 = 0; s2 < 16; ++s2) den[s2] = 0.f;
#pragma unroll
    for (int r = 0; r < 16; ++r) {
        float c = v[r];
        const float* row = &G[r * 16];
#pragma unroll
        for (int s2 = 0; s2 < 16; ++s2) den[s2] = fmaf(c, row[s2], den[s2]);
    }
}

// ---------------- init ----------------
__global__ void k_copy_bases(const float* __restrict__ src) {
    size_t i = (size_t)blockIdx.x * 256 + threadIdx.x;
    reinterpret_cast<float4*>(g_bases)[i] = reinterpret_cast<const float4*>(src)[i];
}

// initial BtB gram partials (only needed once, for bases0). grid (NBTB, BS), block 256
__global__ void k_btb0() {
    const int b  = blockIdx.y;
    const int sl = blockIdx.x;
    const int t  = threadIdx.x;
    const int r   = t & 15;
    const int sq  = (t >> 4) & 3;
    const int sub = t >> 6;
    const float* Ab = g_bases + (size_t)b * DD * RR;
    float4 acc = make_float4(0.f, 0.f, 0.f, 0.f);
    const int dend = sl * 128 + 128;
    for (int d = sl * 128 + sub; d < dend; d += 4) {
        const float* row = Ab + (size_t)d * RR;
        float4 aq = *reinterpret_cast<const float4*>(row + sq * 4);
        float  ar = row[r];
        acc.x = fmaf(ar, aq.x, acc.x);
        acc.y = fmaf(ar, aq.y, acc.y);
        acc.z = fmaf(ar, aq.z, acc.z);
        acc.w = fmaf(ar, aq.w, acc.w);
    }
    __shared__ float4 red[256];
    red[t] = acc;
    __syncthreads();
    if (t < 64) {
        float4 a0 = red[t], a1 = red[t + 64], a2 = red[t + 128], a3 = red[t + 192];
        float4 s;
        s.x = a0.x + a1.x + a2.x + a3.x;
        s.y = a0.y + a1.y + a2.y + a3.y;
        s.z = a0.z + a1.z + a2.z + a3.z;
        s.w = a0.w + a1.w + a2.w + a3.w;
        int rr_ = t & 15, sq_ = t >> 4;
        *reinterpret_cast<float4*>(g_btbp + ((size_t)b * NBTB + sl) * 256 + rr_ * 16 + sq_ * 4) = s;
    }
}

// ---------------- P pass: Ppart[b][ds][n][r], 512-d slices, no x staging ----------------
// grid (4, NSLICE, BS), block 128. Thread owns one n row; loads full 128B lines of its row.
__global__ void __launch_bounds__(128) k_pmat(const float* __restrict__ x) {
    __shared__ float bss[512 * RR];   // 32 KB bases slice

    const int tid = threadIdx.x;
    const int nc  = blockIdx.x;
    const int ds  = blockIdx.y;
    const int b   = blockIdx.z;
    {
        const float4* s = reinterpret_cast<const float4*>(
            g_bases + ((size_t)b * DD + (size_t)ds * 512) * RR);
        float4* dst = reinterpret_cast<float4*>(bss);
#pragma unroll
        for (int i = 0; i < 16; ++i) dst[tid + i * 128] = s[tid + i * 128];
    }
    __syncthreads();

    const int n = nc * 128 + tid;
    float acc[16];
#pragma unroll
    for (int r = 0; r < 16; ++r) acc[r] = 0.f;

    const float* xr = x + ((size_t)b * NN + n) * DD + (size_t)ds * 512;

#pragma unroll 1
    for (int d0 = 0; d0 < 512; d0 += 32) {
        float4 xv[8];
#pragma unroll
        for (int u = 0; u < 8; ++u)
            xv[u] = *reinterpret_cast<const float4*>(xr + d0 + u * 4);
#pragma unroll
        for (int u = 0; u < 8; ++u) {
            const float* brow = &bss[(d0 + u * 4) * RR];
            fma16(acc, xv[u].x, brow);
            fma16(acc, xv[u].y, brow + RR);
            fma16(acc, xv[u].z, brow + 2 * RR);
            fma16(acc, xv[u].w, brow + 3 * RR);
        }
    }
    store16(g_Ppart + (((size_t)b * NSLICE + ds) * NN + n) * RR, acc);
}

// ---------------- coef kernels (reduce partials + update + fused CtC gram) ----------------
__device__ __forceinline__ void coef_body(bool init) {
    __shared__ float btbs[256];
    __shared__ float smcf[128][17];
    const int tid = threadIdx.x;
    const int nc  = blockIdx.x;
    const int b   = blockIdx.y;

    // reduce BtB partials
    for (int j = tid; j < 256; j += 128) {
        float s = 0.f;
#pragma unroll
        for (int sl = 0; sl < NBTB; ++sl) s += g_btbp[((size_t)b * NBTB + sl) * 256 + j];
        btbs[j] = s;
    }

    // gather P
    const int n = nc * 128 + tid;
    float p[16];
#pragma unroll
    for (int r = 0; r < 16; ++r) p[r] = 0.f;
#pragma unroll
    for (int sl = 0; sl < NSLICE; ++sl) {
        const float4* pp = reinterpret_cast<const float4*>(
            g_Ppart + (((size_t)b * NSLICE + sl) * NN + n) * RR);
#pragma unroll
        for (int q = 0; q < 4; ++q) {
            float4 v = pp[q];
            p[4*q+0] += v.x; p[4*q+1] += v.y; p[4*q+2] += v.z; p[4*q+3] += v.w;
        }
    }

    float cf[16];
    if (init) {
        float m = p[0];
#pragma unroll
        for (int r = 1; r < 16; ++r) m = fmaxf(m, p[r]);
        float s = 0.f;
#pragma unroll
        for (int r = 0; r < 16; ++r) { cf[r] = __expf(INVT * (p[r] - m)); s += cf[r]; }
        float inv = 1.f / s;
#pragma unroll
        for (int r = 0; r < 16; ++r) cf[r] *= inv;
    } else {
        load16(g_coef + ((size_t)b * NN + n) * RR, cf);
    }
    __syncthreads();   // btbs ready

    float den[16];
    mat16(den, cf, btbs);
#pragma unroll
    for (int r = 0; r < 16; ++r) cf[r] = cf[r] * p[r] / (den[r] + EPSV);
    store16(g_coef + ((size_t)b * NN + n) * RR, cf);

    // fused CtC gram partial (new coef)
#pragma unroll
    for (int r = 0; r < 16; ++r) smcf[tid][r] = cf[r];
    __syncthreads();
#pragma unroll
    for (int k = 0; k < 2; ++k) {
        int p2 = tid + k * 128;
        int r = p2 >> 4, s2 = p2 & 15;
        float s = 0.f;
#pragma unroll 8
        for (int i = 0; i < 128; ++i) s = fmaf(smcf[i][r], smcf[i][s2], s);
        g_ctcp[((size_t)b * NCTC + nc) * 256 + p2] = s;
    }
}
__global__ void __launch_bounds__(128) k_coef_initupd() { coef_body(true); }   // grid (4, BS)
__global__ void __launch_bounds__(128) k_coef_upd()     { coef_body(false); }  // grid (4, BS)

// ---------------- Q pass fused: Q + bases update + BtB gram partial ----------------
// grid (32, BS), block 128. Thread owns one d.
__global__ void __launch_bounds__(128) k_qmat(const float* __restrict__ x) {
    __shared__ float cfs[NN * RR];   // 32 KB coef (aliased for gram at the end)
    __shared__ float ctcs[256];
    const int tid = threadIdx.x;
    const int dc  = blockIdx.x;
    const int b   = blockIdx.y;
    {
        const float4* s = reinterpret_cast<const float4*>(g_coef + (size_t)b * NN * RR);
        float4* dst = reinterpret_cast<float4*>(cfs);
#pragma unroll
        for (int i = 0; i < 16; ++i) dst[tid + i * 128] = s[tid + i * 128];
    }
    for (int j = tid; j < 256; j += 128) {
        float s = 0.f;
#pragma unroll
        for (int sl = 0; sl < NCTC; ++sl) s += g_ctcp[((size_t)b * NCTC + sl) * 256 + j];
        ctcs[j] = s;
    }
    __syncthreads();

    const int d = dc * 128 + tid;
    float acc[16];
#pragma unroll
    for (int r = 0; r < 16; ++r) acc[r] = 0.f;

    const float* xb = x + (size_t)b * NN * DD + d;
#pragma unroll 1
    for (int n0 = 0; n0 < NN; n0 += 16) {
        float xv[16];
#pragma unroll
        for (int u = 0; u < 16; ++u) xv[u] = xb[(size_t)(n0 + u) * DD];
#pragma unroll
        for (int u = 0; u < 16; ++u) fma16(acc, xv[u], &cfs[(n0 + u) * RR]);
    }

    // bases multiplicative update
    float* brow = g_bases + ((size_t)b * DD + d) * RR;
    float bs[16];
    load16(brow, bs);
    float den[16];
    mat16(den, bs, ctcs);
#pragma unroll
    for (int r = 0; r < 16; ++r) bs[r] = bs[r] * acc[r] / (den[r] + EPSV);
    store16(brow, bs);

    // fused BtB gram partial from NEW bases (alias cfs smem)
    __syncthreads();
    float (*smb)[17] = reinterpret_cast<float (*)[17]>(cfs);
#pragma unroll
    for (int r = 0; r < 16; ++r) smb[tid][r] = bs[r];
    __syncthreads();
#pragma unroll
    for (int k = 0; k < 2; ++k) {
        int p2 = tid + k * 128;
        int r = p2 >> 4, s2 = p2 & 15;
        float s = 0.f;
#pragma unroll 8
        for (int i = 0; i < 128; ++i) s = fmaf(smb[i][r], smb[i][s2], s);
        g_btbp[((size_t)b * NBTB + dc) * 256 + p2] = s;
    }
}

// ---------------- reconstruction: out[b][n][d] = sum_r bases[d][r]*coef[n][r] ----------------
// grid (32, BS), block 128
__global__ void __launch_bounds__(128) k_out(float* __restrict__ out) {
    __shared__ float cfs[NN * RR];
    const int tid = threadIdx.x;
    const int dc  = blockIdx.x;
    const int b   = blockIdx.y;
    {
        const float4* s = reinterpret_cast<const float4*>(g_coef + (size_t)b * NN * RR);
        float4* dst = reinterpret_cast<float4*>(cfs);
#pragma unroll
        for (int i = 0; i < 16; ++i) dst[tid + i * 128] = s[tid + i * 128];
    }
    __syncthreads();

    const int d = dc * 128 + tid;
    float bs[16];
    load16(g_bases + ((size_t)b * DD + d) * RR, bs);

    float* ob = out + (size_t)b * NN * DD + d;
#pragma unroll 4
    for (int n = 0; n < NN; ++n) {
        const float4* c4 = reinterpret_cast<const float4*>(&cfs[n * RR]);
        float o0 = 0.f, o1 = 0.f, o2 = 0.f, o3 = 0.f;
#pragma unroll
        for (int q = 0; q < 4; ++q) {
            float4 c = c4[q];
            o0 = fmaf(bs[4*q+0], c.x, o0);
            o1 = fmaf(bs[4*q+1], c.y, o1);
            o2 = fmaf(bs[4*q+2], c.z, o2);
            o3 = fmaf(bs[4*q+3], c.w, o3);
        }
        ob[(size_t)n * DD] = (o0 + o1) + (o2 + o3);
    }
}

// ---------------- launch ----------------
extern "C" void kernel_launch(void* const* d_in, const int* in_sizes, int n_in,
                              void* d_out, int out_size) {
    (void)in_sizes; (void)n_in; (void)out_size;
    const float* x     = (const float*)d_in[0];
    const float* bases = (const float*)d_in[1];
    float* out = (float*)d_out;

    k_copy_bases<<<(BS * DD * RR / 4) / 256, 256>>>(bases);
    k_btb0<<<dim3(NBTB, BS), 256>>>();

    // softmax init + first coef update (bases unchanged between them)
    k_pmat<<<dim3(4, NSLICE, BS), 128>>>(x);
    k_coef_initupd<<<dim3(4, BS), 128>>>();

    // 7 bases updates, interleaved with coef updates 2..8
    for (int it = 0; it < 7; ++it) {
        k_qmat<<<dim3(32, BS), 128>>>(x);       // bases update + BtB gram
        k_pmat<<<dim3(4, NSLICE, BS), 128>>>(x);
        k_coef_upd<<<dim3(4, BS), 128>>>();     // coef update + CtC gram
    }

    // reconstruction
    k_out<<<dim3(32, BS), 128>>>(out);
}

// round 4
// speedup vs baseline: 2.1963x; 1.2670x over previous
#include <cuda_runtime.h>

#define BS   16
#define DD   4096
#define NN   512
#define RR   16
#define EPSV 1e-6f
#define INVT 100.0f

#define NSLICE 8      // d-slices for P partials (512 d each)
#define NBTB   32     // btb gram partial slices
#define NCTC   4      // ctc gram partial slices

// ---------------- scratch ----------------
__device__ float g_bases[BS * DD * RR];            // 4 MB
__device__ float g_coef [BS * NN * RR];            // 512 KB
__device__ float g_Ppart[BS * NSLICE * NN * RR];   // 4 MB
__device__ float g_btbp [BS * NBTB * 256];
__device__ float g_ctcp [BS * NCTC * 256];

typedef unsigned long long u64;

// ---------------- packed f32x2 helpers (sm_103a FFMA2) ----------------
__device__ __forceinline__ void ffma2(u64& acc, u64 a, u64 b) {
    asm("fma.rn.f32x2 %0, %1, %2, %3;" : "=l"(acc) : "l"(a), "l"(b), "l"(acc));
}
__device__ __forceinline__ u64 packf2(float lo, float hi) {
    u64 r; asm("mov.b64 %0, {%1, %2};" : "=l"(r) : "f"(lo), "f"(hi)); return r;
}
__device__ __forceinline__ void unpackf2(u64 v, float& lo, float& hi) {
    asm("mov.b64 {%0, %1}, %2;" : "=f"(lo), "=f"(hi) : "l"(v));
}

// ---------------- helpers ----------------
__device__ __forceinline__ void load16(const float* __restrict__ src, float* v) {
    const float4* s4 = reinterpret_cast<const float4*>(src);
#pragma unroll
    for (int q = 0; q < 4; ++q) {
        float4 t = s4[q];
        v[4*q+0] = t.x; v[4*q+1] = t.y; v[4*q+2] = t.z; v[4*q+3] = t.w;
    }
}
__device__ __forceinline__ void store16(float* __restrict__ dst, const float* v) {
    float4* d4 = reinterpret_cast<float4*>(dst);
#pragma unroll
    for (int q = 0; q < 4; ++q)
        d4[q] = make_float4(v[4*q+0], v[4*q+1], v[4*q+2], v[4*q+3]);
}
// acc2[8] += (xv,xv) * row[16 floats as 8 pairs]   — 8 FFMA2
__device__ __forceinline__ void fma16_2(u64* acc2, u64 xv2, const float* __restrict__ row) {
    const ulonglong2* r2 = reinterpret_cast<const ulonglong2*>(row);
#pragma unroll
    for (int q = 0; q < 4; ++q) {
        ulonglong2 p = r2[q];
        ffma2(acc2[2*q+0], xv2, p.x);
        ffma2(acc2[2*q+1], xv2, p.y);
    }
}
__device__ __forceinline__ void unpack_acc(const u64* acc2, float* v) {
#pragma unroll
    for (int q = 0; q < 8; ++q) unpackf2(acc2[q], v[2*q], v[2*q+1]);
}
// den[s] = sum_r v[r] * G[r][s]
__device__ __forceinline__ void mat16(float* den, const float* v, const float* __restrict__ G) {
#pragma unroll
    for (int s2 = 0; s2 < 16; ++s2) den[s2] = 0.f;
#pragma unroll
    for (int r = 0; r < 16; ++r) {
        float c = v[r];
        const float* row = &G[r * 16];
#pragma unroll
        for (int s2 = 0; s2 < 16; ++s2) den[s2] = fmaf(c, row[s2], den[s2]);
    }
}

// ---------------- init ----------------
__global__ void k_copy_bases(const float* __restrict__ src) {
    size_t i = (size_t)blockIdx.x * 256 + threadIdx.x;
    reinterpret_cast<float4*>(g_bases)[i] = reinterpret_cast<const float4*>(src)[i];
}

// initial BtB gram partials from INPUT bases. grid (NBTB, BS), block 256
__global__ void k_btb0(const float* __restrict__ src) {
    const int b  = blockIdx.y;
    const int sl = blockIdx.x;
    const int t  = threadIdx.x;
    const int r   = t & 15;
    const int sq  = (t >> 4) & 3;
    const int sub = t >> 6;
    const float* Ab = src + (size_t)b * DD * RR;
    float4 acc = make_float4(0.f, 0.f, 0.f, 0.f);
    const int dend = sl * 128 + 128;
    for (int d = sl * 128 + sub; d < dend; d += 4) {
        const float* row = Ab + (size_t)d * RR;
        float4 aq = *reinterpret_cast<const float4*>(row + sq * 4);
        float  ar = row[r];
        acc.x = fmaf(ar, aq.x, acc.x);
        acc.y = fmaf(ar, aq.y, acc.y);
        acc.z = fmaf(ar, aq.z, acc.z);
        acc.w = fmaf(ar, aq.w, acc.w);
    }
    __shared__ float4 red[256];
    red[t] = acc;
    __syncthreads();
    if (t < 64) {
        float4 a0 = red[t], a1 = red[t + 64], a2 = red[t + 128], a3 = red[t + 192];
        float4 s;
        s.x = a0.x + a1.x + a2.x + a3.x;
        s.y = a0.y + a1.y + a2.y + a3.y;
        s.z = a0.z + a1.z + a2.z + a3.z;
        s.w = a0.w + a1.w + a2.w + a3.w;
        int rr_ = t & 15, sq_ = t >> 4;
        *reinterpret_cast<float4*>(g_btbp + ((size_t)b * NBTB + sl) * 256 + rr_ * 16 + sq_ * 4) = s;
    }
}

// ---------------- P pass: register-pipelined staged, FFMA2 ----------------
// grid (4, NSLICE, BS), block 128. smem: bss 32KB + xs 16.9KB
__global__ void __launch_bounds__(128) k_pmat(const float* __restrict__ x) {
    __shared__ float bss[512 * RR];
    __shared__ float xs[128][33];   // stride 33: conflict-free scalar STS & LDS

    const int tid = threadIdx.x;
    const int nc  = blockIdx.x;
    const int ds  = blockIdx.y;
    const int b   = blockIdx.z;

    // stage bases slice
    {
        const float4* s = reinterpret_cast<const float4*>(
            g_bases + ((size_t)b * DD + (size_t)ds * 512) * RR);
        float4* dst = reinterpret_cast<float4*>(bss);
#pragma unroll
        for (int i = 0; i < 16; ++i) dst[tid + i * 128] = s[tid + i * 128];
    }

    const float* xbase = x + ((size_t)b * NN + (size_t)nc * 128) * DD + (size_t)ds * 512;
    const int srow = tid >> 3;          // staging row within 4-row group step
    const int sc4  = tid & 7;           // float4 column

    u64 acc2[8];
#pragma unroll
    for (int q = 0; q < 8; ++q) acc2[q] = 0ull;

    // preload tile 0: 8 float4 per thread (rows srow + k*16)
    float4 pre[8];
#pragma unroll
    for (int k = 0; k < 8; ++k)
        pre[k] = *reinterpret_cast<const float4*>(xbase + (size_t)(srow + k * 16) * DD + sc4 * 4);

    __syncthreads();   // bss ready

#pragma unroll 1
    for (int t0 = 0; t0 < 512; t0 += 32) {
        // store staged tile (conflict-free scalar STS: bank = (row + 4*c4) distinct)
#pragma unroll
        for (int k = 0; k < 8; ++k) {
            float* dp = &xs[srow + k * 16][sc4 * 4];
            dp[0] = pre[k].x; dp[1] = pre[k].y; dp[2] = pre[k].z; dp[3] = pre[k].w;
        }
        __syncthreads();
        // prefetch next tile into registers (hidden under compute)
        if (t0 + 32 < 512) {
#pragma unroll
            for (int k = 0; k < 8; ++k)
                pre[k] = *reinterpret_cast<const float4*>(
                    xbase + (size_t)(srow + k * 16) * DD + (t0 + 32) + sc4 * 4);
        }
        // compute: thread owns row tid
#pragma unroll
        for (int j = 0; j < 32; ++j) {
            float xv = xs[tid][j];
            u64 xv2 = packf2(xv, xv);
            fma16_2(acc2, xv2, &bss[(t0 + j) * RR]);   // broadcast LDS.128
        }
        __syncthreads();
    }

    float acc[16];
    unpack_acc(acc2, acc);
    const int n = nc * 128 + tid;
    store16(g_Ppart + (((size_t)b * NSLICE + ds) * NN + n) * RR, acc);
}

// ---------------- coef kernels ----------------
__device__ __forceinline__ void coef_body(bool init) {
    __shared__ float btbs[256];
    __shared__ float smcf[128][17];
    const int tid = threadIdx.x;
    const int nc  = blockIdx.x;
    const int b   = blockIdx.y;

    // reduce BtB partials (float4, 64 threads)
    if (tid < 64) {
        float4 s = make_float4(0.f, 0.f, 0.f, 0.f);
#pragma unroll
        for (int sl = 0; sl < NBTB; ++sl) {
            float4 v = *reinterpret_cast<const float4*>(
                g_btbp + ((size_t)b * NBTB + sl) * 256 + tid * 4);
            s.x += v.x; s.y += v.y; s.z += v.z; s.w += v.w;
        }
        *reinterpret_cast<float4*>(&btbs[tid * 4]) = s;
    }

    // gather P
    const int n = nc * 128 + tid;
    float p[16];
#pragma unroll
    for (int r = 0; r < 16; ++r) p[r] = 0.f;
#pragma unroll
    for (int sl = 0; sl < NSLICE; ++sl) {
        const float4* pp = reinterpret_cast<const float4*>(
            g_Ppart + (((size_t)b * NSLICE + sl) * NN + n) * RR);
#pragma unroll
        for (int q = 0; q < 4; ++q) {
            float4 v = pp[q];
            p[4*q+0] += v.x; p[4*q+1] += v.y; p[4*q+2] += v.z; p[4*q+3] += v.w;
        }
    }

    float cf[16];
    if (init) {
        float m = p[0];
#pragma unroll
        for (int r = 1; r < 16; ++r) m = fmaxf(m, p[r]);
        float s = 0.f;
#pragma unroll
        for (int r = 0; r < 16; ++r) { cf[r] = __expf(INVT * (p[r] - m)); s += cf[r]; }
        float inv = 1.f / s;
#pragma unroll
        for (int r = 0; r < 16; ++r) cf[r] *= inv;
    } else {
        load16(g_coef + ((size_t)b * NN + n) * RR, cf);
    }
    __syncthreads();

    float den[16];
    mat16(den, cf, btbs);
#pragma unroll
    for (int r = 0; r < 16; ++r) cf[r] = cf[r] * p[r] / (den[r] + EPSV);
    store16(g_coef + ((size_t)b * NN + n) * RR, cf);

    // fused CtC gram partial (new coef)
#pragma unroll
    for (int r = 0; r < 16; ++r) smcf[tid][r] = cf[r];
    __syncthreads();
#pragma unroll
    for (int k = 0; k < 2; ++k) {
        int p2 = tid + k * 128;
        int r = p2 >> 4, s2 = p2 & 15;
        float s = 0.f;
#pragma unroll 8
        for (int i = 0; i < 128; ++i) s = fmaf(smcf[i][r], smcf[i][s2], s);
        g_ctcp[((size_t)b * NCTC + nc) * 256 + p2] = s;
    }
}
__global__ void __launch_bounds__(128) k_coef_initupd() { coef_body(true); }   // grid (4, BS)
__global__ void __launch_bounds__(128) k_coef_upd()     { coef_body(false); }  // grid (4, BS)

// ---------------- Q pass fused: Q + bases update + BtB gram partial, FFMA2 ----------------
// grid (32, BS), block 128
__global__ void __launch_bounds__(128) k_qmat(const float* __restrict__ x) {
    __shared__ float cfs[NN * RR];
    __shared__ float ctcs[256];
    const int tid = threadIdx.x;
    const int dc  = blockIdx.x;
    const int b   = blockIdx.y;
    {
        const float4* s = reinterpret_cast<const float4*>(g_coef + (size_t)b * NN * RR);
        float4* dst = reinterpret_cast<float4*>(cfs);
#pragma unroll
        for (int i = 0; i < 16; ++i) dst[tid + i * 128] = s[tid + i * 128];
    }
    if (tid < 64) {
        float4 s = make_float4(0.f, 0.f, 0.f, 0.f);
#pragma unroll
        for (int sl = 0; sl < NCTC; ++sl) {
            float4 v = *reinterpret_cast<const float4*>(
                g_ctcp + ((size_t)b * NCTC + sl) * 256 + tid * 4);
            s.x += v.x; s.y += v.y; s.z += v.z; s.w += v.w;
        }
        *reinterpret_cast<float4*>(&ctcs[tid * 4]) = s;
    }
    __syncthreads();

    const int d = dc * 128 + tid;
    u64 acc2[8];
#pragma unroll
    for (int q = 0; q < 8; ++q) acc2[q] = 0ull;

    const float* xb = x + (size_t)b * NN * DD + d;
#pragma unroll 1
    for (int n0 = 0; n0 < NN; n0 += 16) {
        float xv[16];
#pragma unroll
        for (int u = 0; u < 16; ++u) xv[u] = xb[(size_t)(n0 + u) * DD];
#pragma unroll
        for (int u = 0; u < 16; ++u)
            fma16_2(acc2, packf2(xv[u], xv[u]), &cfs[(n0 + u) * RR]);
    }
    float acc[16];
    unpack_acc(acc2, acc);

    // bases multiplicative update
    float* brow = g_bases + ((size_t)b * DD + d) * RR;
    float bs[16];
    load16(brow, bs);
    float den[16];
    mat16(den, bs, ctcs);
#pragma unroll
    for (int r = 0; r < 16; ++r) bs[r] = bs[r] * acc[r] / (den[r] + EPSV);
    store16(brow, bs);

    // fused BtB gram partial from NEW bases (alias cfs smem)
    __syncthreads();
    float (*smb)[17] = reinterpret_cast<float (*)[17]>(cfs);
#pragma unroll
    for (int r = 0; r < 16; ++r) smb[tid][r] = bs[r];
    __syncthreads();
#pragma unroll
    for (int k = 0; k < 2; ++k) {
        int p2 = tid + k * 128;
        int r = p2 >> 4, s2 = p2 & 15;
        float s = 0.f;
#pragma unroll 8
        for (int i = 0; i < 128; ++i) s = fmaf(smb[i][r], smb[i][s2], s);
        g_btbp[((size_t)b * NBTB + dc) * 256 + p2] = s;
    }
}

// ---------------- reconstruction, FFMA2 dot ----------------
// grid (32, BS), block 128
__global__ void __launch_bounds__(128) k_out(float* __restrict__ out) {
    __shared__ float cfs[NN * RR];
    const int tid = threadIdx.x;
    const int dc  = blockIdx.x;
    const int b   = blockIdx.y;
    {
        const float4* s = reinterpret_cast<const float4*>(g_coef + (size_t)b * NN * RR);
        float4* dst = reinterpret_cast<float4*>(cfs);
#pragma unroll
        for (int i = 0; i < 16; ++i) dst[tid + i * 128] = s[tid + i * 128];
    }
    __syncthreads();

    const int d = dc * 128 + tid;
    float bs[16];
    load16(g_bases + ((size_t)b * DD + d) * RR, bs);
    u64 bs2[8];
#pragma unroll
    for (int q = 0; q < 8; ++q) bs2[q] = packf2(bs[2*q], bs[2*q+1]);

    float* ob = out + (size_t)b * NN * DD + d;
#pragma unroll 4
    for (int n = 0; n < NN; ++n) {
        const ulonglong2* c2 = reinterpret_cast<const ulonglong2*>(&cfs[n * RR]);
        u64 o2a = 0ull, o2b = 0ull;
#pragma unroll
        for (int q = 0; q < 4; ++q) {
            ulonglong2 p = c2[q];
            ffma2(o2a, bs2[2*q+0], p.x);
            ffma2(o2b, bs2[2*q+1], p.y);
        }
        float a0, a1, b0, b1;
        unpackf2(o2a, a0, a1);
        unpackf2(o2b, b0, b1);
        ob[(size_t)n * DD] = (a0 + a1) + (b0 + b1);
    }
}

// ---------------- launch ----------------
extern "C" void kernel_launch(void* const* d_in, const int* in_sizes, int n_in,
                              void* d_out, int out_size) {
    (void)in_sizes; (void)n_in; (void)out_size;
    const float* x     = (const float*)d_in[0];
    const float* bases = (const float*)d_in[1];
    float* out = (float*)d_out;

    k_copy_bases<<<(BS * DD * RR / 4) / 256, 256>>>(bases);
    k_btb0<<<dim3(NBTB, BS), 256>>>(bases);

    k_pmat<<<dim3(4, NSLICE, BS), 128>>>(x);
    k_coef_initupd<<<dim3(4, BS), 128>>>();

    for (int it = 0; it < 7; ++it) {
        k_qmat<<<dim3(32, BS), 128>>>(x);        // bases update + BtB gram
        k_pmat<<<dim3(4, NSLICE, BS), 128>>>(x);
        k_coef_upd<<<dim3(4, BS), 128>>>();      // coef update + CtC gram
    }

    k_out<<<dim3(32, BS), 128>>>(out);
}